// round 12
// baseline (speedup 1.0000x reference)
#include <cuda_runtime.h>
#include <cstdint>

// DigitCaps dynamic routing, fused.
// b_t[i,j] = u_hat[b,i,j,:] . Vsum_t[b,j,:], Vsum_t = sum_{tau<t} v_tau
// W prepacked [chunk][g][e][dpair][j]; ONE cp.async.bulk per chunk; 3-slot ring.
// FIRST sweep: 4 batches/thread. non-FIRST: 4 batches/thread with k-split
// (each thread owns half the d-pairs; logit partials exchanged via smem).

#define B_      512
#define NI      1152
#define NJ      10
#define DI      8
#define DO      16

#define THREADS 256
#define BT      8        // non-FIRST: batches per block
#define BTF     16       // FIRST: batches per block
#define G_      6        // i's per chunk
#define ISPLITS 8
#define ICHUNK  144      // NI / ISPLITS
#define NCHUNK  24       // ICHUNK / G_
#define NCHUNK_TOTAL (ISPLITS * NCHUNK)   // 192
#define NPART   ISPLITS  // 8 partials per (b,j)

#define WTILE_ULL  644
#define WBUF_ULL   (G_ * WTILE_ULL)       // 3864 ull per ring slot
#define WBUF       (WBUF_ULL * 2)         // 7728 words
#define NBUF    3
#define VROW    18
#define CHUNK_BYTES (WBUF * 4)            // 30912

// sweep (non-FIRST) smem: ring + vsum(8*10*18=1440) + xch(24*10*4=960) + mbar
#define XCH_WORDS   (24 * NJ * 4)
#define MBAR_OFF_S  (NBUF * WBUF + BT * NJ * VROW + XCH_WORDS)
// first smem: ring + vsum-area-unused + mbar at legacy offset
#define MBAR_OFF_F  (NBUF * WBUF + BTF * NJ * VROW)
#define SMEM_WORDS  (MBAR_OFF_F + 8)      // 26072 (max of both kernels)

__device__ float g_wpad[(size_t)NCHUNK_TOTAL * WBUF];
__device__ float g_partial[(size_t)B_ * NPART * NJ * DO];
__device__ float g_vsum[B_ * NJ * DO];

using ull = unsigned long long;

__device__ __forceinline__ ull fma2(ull a, ull b, ull c) {
    ull d; asm("fma.rn.f32x2 %0, %1, %2, %3;" : "=l"(d) : "l"(a), "l"(b), "l"(c)); return d;
}
__device__ __forceinline__ ull bcast2(float x) {
    ull d; asm("mov.b64 %0, {%1, %1};" : "=l"(d) : "f"(x)); return d;
}
__device__ __forceinline__ ull pack2(float x, float y) {
    ull d; asm("mov.b64 %0, {%1, %2};" : "=l"(d) : "f"(x), "f"(y)); return d;
}
__device__ __forceinline__ float sum2(ull a) {
    float l, h; asm("mov.b64 {%0, %1}, %2;" : "=f"(l), "=f"(h) : "l"(a)); return l + h;
}
__device__ __forceinline__ void st2(float* p, ull v) { *(ull*)p = v; }

__device__ __forceinline__ void mbar_init(uint32_t addr, uint32_t count) {
    asm volatile("mbarrier.init.shared.b64 [%0], %1;" :: "r"(addr), "r"(count) : "memory");
}
__device__ __forceinline__ void mbar_wait(uint32_t addr, uint32_t parity) {
    asm volatile(
        "{\n\t.reg .pred P;\n\t"
        "WL_%=:\n\t"
        "mbarrier.try_wait.parity.acquire.cta.shared::cta.b64 P, [%0], %1, 0x989680;\n\t"
        "@P bra.uni WD_%=;\n\t"
        "bra.uni WL_%=;\n\t"
        "WD_%=:\n\t}"
        :: "r"(addr), "r"(parity) : "memory");
}

__device__ __forceinline__ void issue_chunk(int chunk, int slot,
                                            uint32_t sbase, uint32_t mbase, int tid) {
    if (tid == 0) {
        uint32_t mbar = mbase + slot * 8;
        asm volatile("mbarrier.arrive.expect_tx.shared.b64 _, [%0], %1;"
                     :: "r"(mbar), "r"((uint32_t)CHUNK_BYTES) : "memory");
        const float* src = g_wpad + (size_t)chunk * WBUF;
        uint32_t dst = sbase + (uint32_t)(slot * WBUF) * 4;
        asm volatile(
            "cp.async.bulk.shared::cluster.global.mbarrier::complete_tx::bytes "
            "[%0], [%1], %2, [%3];"
            :: "r"(dst), "l"(src), "r"((uint32_t)CHUNK_BYTES), "r"(mbar) : "memory");
    }
}

// W[i][j][e][d] -> g_wpad ull[chunk*WBUF_ULL + g*644 + e*80 + k*10 + j]
__global__ void prepack_kernel(const float* __restrict__ W) {
    int t = blockIdx.x * blockDim.x + threadIdx.x;
    if (t >= NI * NJ * DI) return;
    int e = t % DI;
    int r = t / DI;
    int j = r % NJ;
    int i = r / NJ;
    int chunk = i / G_;
    int g = i - chunk * G_;
    const float4* src = (const float4*)(W + (((size_t)(i * NJ + j)) * DI + e) * DO);
    float4 v0 = src[0], v1 = src[1], v2 = src[2], v3 = src[3];
    ull* dst = (ull*)g_wpad + (size_t)chunk * WBUF_ULL + g * WTILE_ULL + e * 80 + j;
    dst[0]  = pack2(v0.x, v0.y);
    dst[10] = pack2(v0.z, v0.w);
    dst[20] = pack2(v1.x, v1.y);
    dst[30] = pack2(v1.z, v1.w);
    dst[40] = pack2(v2.x, v2.y);
    dst[50] = pack2(v2.z, v2.w);
    dst[60] = pack2(v3.x, v3.y);
    dst[70] = pack2(v3.z, v3.w);
}

// ---------------- FIRST iteration: uniform c=0.1, 4 batches/thread ----------------
__global__ void __launch_bounds__(THREADS, 2)
sweep_first_kernel(const float* __restrict__ u) {
    extern __shared__ float smem[];
    float* wst = smem;
    float* red = smem;

    const int tid  = threadIdx.x;
    const int lane = tid & 31;
    const int warp = tid >> 5;
    const int seg  = lane / 10;
    const bool active = (seg < 3);
    const int j    = lane - seg * 10;
    const int unit = warp * 3 + (active ? seg : 0);
    const int bq   = unit & 3;
    const int g    = unit >> 2;

    const int c0g   = blockIdx.x * NCHUNK;
    const int i0    = blockIdx.x * ICHUNK;
    const int bbase = blockIdx.y * BTF;

    uint32_t smem_base = (uint32_t)__cvta_generic_to_shared(wst);
    uint32_t mbar_base = (uint32_t)__cvta_generic_to_shared(smem + MBAR_OFF_F);

    if (tid == 0) {
        mbar_init(mbar_base + 0, 1);
        mbar_init(mbar_base + 8, 1);
        mbar_init(mbar_base + 16, 1);
    }
    __syncthreads();

    issue_chunk(c0g, 0, smem_base, mbar_base, tid);
    issue_chunk(c0g + 1, 1, smem_base, mbar_base, tid);

    ull sacc[4][8];
    #pragma unroll
    for (int b = 0; b < 4; b++)
        #pragma unroll
        for (int k = 0; k < 8; k++) sacc[b][k] = 0ULL;

    const int b0 = bbase + bq * 4;
    const float* up = u + (size_t)b0 * NI * DI;

    for (int c = 0; c < NCHUNK; c++) {
        const int buf = c % NBUF;
        const int i = i0 + c * G_ + g;

        float ur[4][8];
        if (active) {
            #pragma unroll
            for (int b = 0; b < 4; b++) {
                const float4* s = (const float4*)(up + (size_t)b * NI * DI + (size_t)i * DI);
                float4 x = s[0], y = s[1];
                ur[b][0]=x.x; ur[b][1]=x.y; ur[b][2]=x.z; ur[b][3]=x.w;
                ur[b][4]=y.x; ur[b][5]=y.y; ur[b][6]=y.z; ur[b][7]=y.w;
            }
        }

        __syncthreads();
        if (c + 2 < NCHUNK)
            issue_chunk(c0g + c + 2, (c + 2) % NBUF, smem_base, mbar_base, tid);

        mbar_wait(mbar_base + buf * 8, (c / NBUF) & 1);

        if (active) {
            const ull* wt = (const ull*)(wst + buf * WBUF) + g * WTILE_ULL + j;
            #pragma unroll
            for (int e = 0; e < 8; e++) {
                const ull* wte = wt + e * 80;
                ull ue0 = bcast2(ur[0][e]);
                ull ue1 = bcast2(ur[1][e]);
                ull ue2 = bcast2(ur[2][e]);
                ull ue3 = bcast2(ur[3][e]);
                #pragma unroll
                for (int k = 0; k < 8; k++) {
                    ull wv = wte[k * 10];
                    sacc[0][k] = fma2(ue0, wv, sacc[0][k]);
                    sacc[1][k] = fma2(ue1, wv, sacc[1][k]);
                    sacc[2][k] = fma2(ue2, wv, sacc[2][k]);
                    sacc[3][k] = fma2(ue3, wv, sacc[3][k]);
                }
            }
        }
    }

    __syncthreads();
    if (active) {
        #pragma unroll
        for (int b = 0; b < 4; b++) {
            int r = ((bq * 4 + b) * 6 + g) * 10 + j;
            #pragma unroll
            for (int k = 0; k < 8; k++)
                st2(red + r * 16 + 2 * k, sacc[b][k]);
        }
    }
    __syncthreads();

    #pragma unroll 1
    for (int idx = tid; idx < BTF * NJ * DO; idx += THREADS) {
        int d  = idx & 15;
        int r  = idx >> 4;
        int jj = r % 10;
        int bt = r / 10;
        float s = 0.f;
        #pragma unroll
        for (int gg = 0; gg < 6; gg++)
            s += red[((bt * 6 + gg) * 10 + jj) * 16 + d];
        s *= 0.1f;
        int b = bbase + bt;
        g_partial[((size_t)(b * NPART + blockIdx.x) * NJ + jj) * DO + d] = s;
    }
}

// ---- non-FIRST: 4 batches/thread, k-split (kh owns 4 d-pairs), smem logit xch ----
__global__ void __launch_bounds__(THREADS, 2)
sweep_kernel(const float* __restrict__ u) {
    extern __shared__ float smem[];
    float* wst = smem;
    float* vsm = smem + NBUF * WBUF;
    float* xch = vsm + BT * NJ * VROW;
    float* red = smem;

    const int tid  = threadIdx.x;
    const int lane = tid & 31;
    const int warp = tid >> 5;
    const int seg  = lane / 10;
    const bool active = (seg < 3);
    const int j    = lane - seg * 10;
    const int unit = warp * 3 + (active ? seg : 0);   // 0..23
    const int kh   = unit & 1;                        // d-pair half
    const int bq   = (unit >> 1) & 1;                 // batch quad
    const int g    = unit >> 2;                       // 0..5

    const int base = seg * 10;
    const int sl5 = base + (j >= 5 ? j - 5 : j + 5);
    const int sl1 = base + (j >= 9 ? j - 9 : j + 1);
    const int sl2 = base + (j >= 8 ? j - 8 : j + 2);
    const int sl4 = base + (j >= 6 ? j - 6 : j + 4);

    const int c0g   = blockIdx.x * NCHUNK;
    const int i0    = blockIdx.x * ICHUNK;
    const int bbase = blockIdx.y * BT;

    uint32_t smem_base = (uint32_t)__cvta_generic_to_shared(wst);
    uint32_t mbar_base = (uint32_t)__cvta_generic_to_shared(smem + MBAR_OFF_S);

    if (tid == 0) {
        mbar_init(mbar_base + 0, 1);
        mbar_init(mbar_base + 8, 1);
        mbar_init(mbar_base + 16, 1);
    }
    for (int idx = tid; idx < BT * NJ * DO; idx += THREADS) {
        vsm[(idx >> 4) * VROW + (idx & 15)] = g_vsum[bbase * NJ * DO + idx];
    }
    __syncthreads();

    issue_chunk(c0g, 0, smem_base, mbar_base, tid);
    issue_chunk(c0g + 1, 1, smem_base, mbar_base, tid);

    ull sacc[4][4];
    #pragma unroll
    for (int b = 0; b < 4; b++)
        #pragma unroll
        for (int k = 0; k < 4; k++) sacc[b][k] = 0ULL;

    const int b0 = bbase + bq * 4;
    const float* up = u + (size_t)b0 * NI * DI;
    // vsum k-half pointer per batch (j-row, offset kh*4 d-pairs = kh*8 floats)
    const float* vsb0 = vsm + ((bq * 4 + 0) * NJ + j) * VROW + kh * 8;

    for (int c = 0; c < NCHUNK; c++) {
        const int buf = c % NBUF;
        const int i = i0 + c * G_ + g;

        float ur[4][8];
        if (active) {
            #pragma unroll
            for (int b = 0; b < 4; b++) {
                const float4* s = (const float4*)(up + (size_t)b * NI * DI + (size_t)i * DI);
                float4 x = s[0], y = s[1];
                ur[b][0]=x.x; ur[b][1]=x.y; ur[b][2]=x.z; ur[b][3]=x.w;
                ur[b][4]=y.x; ur[b][5]=y.y; ur[b][6]=y.z; ur[b][7]=y.w;
            }
        }

        __syncthreads();   // all warps finished a-pass of chunk c-1 -> slot reusable
        if (c + 2 < NCHUNK)
            issue_chunk(c0g + c + 2, (c + 2) % NBUF, smem_base, mbar_base, tid);

        mbar_wait(mbar_base + buf * 8, (c / NBUF) & 1);

        ull a[4][4];
        float pd[4];
        if (active) {
            const ull* wt = (const ull*)(wst + buf * WBUF) + g * WTILE_ULL + kh * 40 + j;
            #pragma unroll
            for (int b = 0; b < 4; b++)
                #pragma unroll
                for (int k = 0; k < 4; k++) a[b][k] = 0ULL;
            #pragma unroll
            for (int e = 0; e < 8; e++) {
                const ull* wte = wt + e * 80;
                ull ue0 = bcast2(ur[0][e]);
                ull ue1 = bcast2(ur[1][e]);
                ull ue2 = bcast2(ur[2][e]);
                ull ue3 = bcast2(ur[3][e]);
                #pragma unroll
                for (int k = 0; k < 4; k++) {
                    ull wv = wte[k * 10];
                    a[0][k] = fma2(ue0, wv, a[0][k]);
                    a[1][k] = fma2(ue1, wv, a[1][k]);
                    a[2][k] = fma2(ue2, wv, a[2][k]);
                    a[3][k] = fma2(ue3, wv, a[3][k]);
                }
            }
            // partial logit over this k-half
            #pragma unroll
            for (int b = 0; b < 4; b++) {
                const ull* vsb = (const ull*)(vsb0 + b * NJ * VROW);
                ull d = 0ULL;
                #pragma unroll
                for (int k = 0; k < 4; k++) d = fma2(a[b][k], vsb[k], d);
                pd[b] = sum2(d);
                xch[(unit * 10 + j) * 4 + b] = pd[b];
            }
        }

        __syncthreads();   // xch visibility between kh partners

        if (active) {
            const int pidx = ((unit ^ 1) * 10 + j) * 4;
            const unsigned M = 0x3FFFFFFFu;
            #pragma unroll
            for (int b = 0; b < 4; b++) {
                float lg = pd[b] + xch[pidx + b];
                float ex = __expf(lg);
                float s5 = ex + __shfl_sync(M, ex, sl5);
                float as = s5 + __shfl_sync(M, s5, sl1);
                float bs = as + __shfl_sync(M, as, sl2);
                float tt = bs + __shfl_sync(M, s5, sl4);
                ull cb = bcast2(__fdividef(ex, tt));
                #pragma unroll
                for (int k = 0; k < 4; k++)
                    sacc[b][k] = fma2(cb, a[b][k], sacc[b][k]);
            }
        }
    }

    // ---- in-block reduction over g ----
    __syncthreads();
    if (active) {
        #pragma unroll
        for (int b = 0; b < 4; b++) {
            int r = ((bq * 4 + b) * 6 + g) * 10 + j;
            #pragma unroll
            for (int k = 0; k < 4; k++)
                st2(red + r * 16 + kh * 8 + 2 * k, sacc[b][k]);
        }
    }
    __syncthreads();

    #pragma unroll 1
    for (int idx = tid; idx < BT * NJ * DO; idx += THREADS) {
        int d  = idx & 15;
        int r  = idx >> 4;
        int jj = r % 10;
        int bt = r / 10;                 // 0..7
        float s = 0.f;
        #pragma unroll
        for (int gg = 0; gg < 6; gg++)
            s += red[((bt * 6 + gg) * 10 + jj) * 16 + d];
        int b = bbase + bt;
        g_partial[((size_t)(b * NPART + blockIdx.x) * NJ + jj) * DO + d] = s;
    }
}

template <bool FIRST, bool LAST>
__global__ void reduce_kernel(float* __restrict__ out) {
    int t = blockIdx.x * blockDim.x + threadIdx.x;
    if (t >= B_ * NJ * 4) return;
    int q = t & 3;
    int j = (t >> 2) % NJ;
    int b = t / (NJ * 4);

    const float4* src = (const float4*)g_partial + ((size_t)(b * NPART) * NJ + j) * 4 + q;
    float4 acc = make_float4(0.f, 0.f, 0.f, 0.f);
    #pragma unroll
    for (int p = 0; p < NPART; p++) {
        float4 x = src[(size_t)p * NJ * 4];
        acc.x += x.x; acc.y += x.y; acc.z += x.z; acc.w += x.w;
    }

    float sq = acc.x * acc.x + acc.y * acc.y + acc.z * acc.z + acc.w * acc.w;
    sq += __shfl_xor_sync(0xFFFFFFFFu, sq, 1);
    sq += __shfl_xor_sync(0xFFFFFFFFu, sq, 2);
    float norm = sqrtf(sq);
    float factor = sq / (norm * (1.f + sq));

    float4 v = make_float4(factor * acc.x, factor * acc.y, factor * acc.z, factor * acc.w);
    if (LAST) {
        ((float4*)out)[(size_t)(b * NJ + j) * 4 + q] = v;
    } else {
        float4* vp = (float4*)g_vsum + (b * NJ + j) * 4 + q;
        if (FIRST) {
            *vp = v;
        } else {
            float4 o = *vp;
            *vp = make_float4(o.x + v.x, o.y + v.y, o.z + v.z, o.w + v.w);
        }
    }
}

extern "C" void kernel_launch(void* const* d_in, const int* in_sizes, int n_in,
                              void* d_out, int out_size) {
    const float* u = (const float*)d_in[0];
    const float* W = (const float*)d_in[1];
    float* out = (float*)d_out;

    const int smem = SMEM_WORDS * 4;
    cudaFuncSetAttribute(sweep_first_kernel, cudaFuncAttributeMaxDynamicSharedMemorySize, smem);
    cudaFuncSetAttribute(sweep_kernel,       cudaFuncAttributeMaxDynamicSharedMemorySize, smem);

    dim3 gridF(ISPLITS, B_ / BTF);                           // 8 x 32
    dim3 grid(ISPLITS, B_ / BT);                             // 8 x 64
    const int rblocks = (B_ * NJ * 4 + 255) / 256;           // 80
    const int pthreads = NI * NJ * DI;
    const int pblocks = (pthreads + 255) / 256;

    prepack_kernel<<<pblocks, 256>>>(W);                      // launch 0
    sweep_first_kernel<<<gridF, THREADS, smem>>>(u);          // launch 1
    reduce_kernel<true, false><<<rblocks, 256>>>(out);        // launch 2
    sweep_kernel<<<grid, THREADS, smem>>>(u);                 // launch 3
    reduce_kernel<false, false><<<rblocks, 256>>>(out);       // launch 4
    sweep_kernel<<<grid, THREADS, smem>>>(u);                 // launch 5  <- ncu -s 5
    reduce_kernel<false, true><<<rblocks, 256>>>(out);        // launch 6
}